// round 1
// baseline (speedup 1.0000x reference)
#include <cuda_runtime.h>
#include <cstdint>
#include <math.h>

// Problem dims (fixed by setup_inputs): x[8, 4096, 1024] f32, requested_r=2048
#define B_   8
#define T_   4096
#define C_   1024
#define K_   2048           // kept tokens per batch (T - requested_r)
#define NK_  2048           // non-kept tokens per batch
#define BT   (B_ * T_)
#define BK   (B_ * K_)

// ---- scratch (static __device__ globals: allocation-free) ----
__device__ float  g_score[BT];
__device__ float  g_invn[BT];
__device__ int    g_keep[BK];
__device__ int    g_nonkept[B_ * NK_];
__device__ int    g_keeprank[BT];
__device__ unsigned long long g_arg[BT];
__device__ int    g_assign[BT];
__device__ float  g_sums[(size_t)BK * C_];   // 64 MB
__device__ float  g_cnt[BK];

__device__ __forceinline__ unsigned int ordf(float f) {
    unsigned int u = __float_as_uint(f);
    return (u & 0x80000000u) ? ~u : (u | 0x80000000u);
}

// ---------------------------------------------------------------
// 1) per-token squared-L2 score (fp64 accumulate) + inverse norm
// ---------------------------------------------------------------
__global__ void score_kernel(const float* __restrict__ x) {
    int tok = blockIdx.x;
    const float* xp = x + (size_t)tok * C_;
    double s = 0.0;
    for (int i = threadIdx.x; i < C_; i += 256) {
        double v = (double)xp[i];
        s += v * v;
    }
    #pragma unroll
    for (int o = 16; o; o >>= 1) s += __shfl_down_sync(0xffffffffu, s, o);
    __shared__ double sm[8];
    if ((threadIdx.x & 31) == 0) sm[threadIdx.x >> 5] = s;
    __syncthreads();
    if (threadIdx.x < 8) {
        double v = sm[threadIdx.x];
        #pragma unroll
        for (int o = 4; o; o >>= 1) v += __shfl_down_sync(0xffu, v, o);
        if (threadIdx.x == 0) {
            float fs = (float)v;
            if ((tok & (T_ - 1)) == 0) fs = 3.402823466e+38f;   // CLS protection
            g_score[tok] = fs;
            g_invn[tok]  = 1.0f / ((float)sqrt(v) + 1e-12f);
        }
    }
}

// ---------------------------------------------------------------
// 2) per-batch exact top-K via bitonic sort (score desc, idx asc),
//    then sort kept / non-kept index lists ascending
// ---------------------------------------------------------------
__global__ void __launch_bounds__(1024) topk_kernel() {
    int b   = blockIdx.x;
    int tid = threadIdx.x;
    __shared__ unsigned long long skey[T_];   // 32 KB

    for (int i = tid; i < T_; i += 1024) {
        unsigned long long k =
            ((unsigned long long)(~ordf(g_score[b * T_ + i])) << 32) | (unsigned int)i;
        skey[i] = k;
        g_keeprank[b * T_ + i] = -1;
    }
    __syncthreads();

    // ascending sort of key => descending score, ascending idx on ties
    for (int k = 2; k <= T_; k <<= 1) {
        for (int j = k >> 1; j > 0; j >>= 1) {
            for (int i = tid; i < T_; i += 1024) {
                int l = i ^ j;
                if (l > i) {
                    unsigned long long a = skey[i], c = skey[l];
                    bool asc = ((i & k) == 0);
                    if ((a > c) == asc) { skey[i] = c; skey[l] = a; }
                }
            }
            __syncthreads();
        }
    }

    // extract indices into int view of the same smem (register round-trip)
    int myi[4];
    #pragma unroll
    for (int r = 0; r < 4; r++)
        myi[r] = (int)(unsigned int)(skey[tid + r * 1024] & 0xFFFFFFFFull);
    __syncthreads();
    int* si = (int*)skey;
    #pragma unroll
    for (int r = 0; r < 4; r++) si[tid + r * 1024] = myi[r];
    __syncthreads();

    // sort both halves (kept [0,2048), non-kept [2048,4096)) ascending
    for (int k = 2; k <= 2048; k <<= 1) {
        for (int j = k >> 1; j > 0; j >>= 1) {
            for (int base = 0; base < T_; base += 2048) {
                for (int i = tid; i < 2048; i += 1024) {
                    int l = i ^ j;
                    if (l > i) {
                        int a = si[base + i], c = si[base + l];
                        bool asc = ((i & k) == 0);
                        if ((a > c) == asc) { si[base + i] = c; si[base + l] = a; }
                    }
                }
            }
            __syncthreads();
        }
    }

    for (int i = tid; i < K_; i += 1024) {
        int t = si[i];
        g_keep[b * K_ + i] = t;
        g_keeprank[b * T_ + t] = i;
    }
    for (int i = tid; i < NK_; i += 1024)
        g_nonkept[b * NK_ + i] = si[2048 + i];
}

// ---------------------------------------------------------------
// 3) zero scratch (sums, cnt, argmax buffer)
// ---------------------------------------------------------------
__global__ void zero_kernel() {
    size_t i = (size_t)blockIdx.x * blockDim.x + threadIdx.x;
    size_t n4 = ((size_t)BK * C_) / 4;
    float4 z = make_float4(0.f, 0.f, 0.f, 0.f);
    float4* p = (float4*)g_sums;
    for (size_t j = i; j < n4; j += (size_t)gridDim.x * blockDim.x) p[j] = z;
    if (i < BK) g_cnt[i] = 0.f;
    if (i < BT) g_arg[i] = 0ull;
}

// ---------------------------------------------------------------
// 4) cosine sim GEMM (non-kept rows x kept centers) with fused
//    row-argmax epilogue. 128x128x8 tile, 8x8 microtile, fp32.
// ---------------------------------------------------------------
__global__ void __launch_bounds__(256) simarg_kernel(const float* __restrict__ x) {
    int b  = blockIdx.z;
    int m0 = blockIdx.y * 128;
    int n0 = blockIdx.x * 128;
    int tid = threadIdx.x;

    __shared__ float As[8][132];
    __shared__ float Bs[8][132];

    int arow  = tid >> 1;      // 0..127 : the tile row this thread stages
    int ahalf = tid & 1;       // which float4 of the 8-wide k-chunk
    int tokA = g_nonkept[b * NK_ + m0 + arow];
    int tokB = g_keep[b * K_ + n0 + arow];
    float invA = g_invn[b * T_ + tokA];
    float invB = g_invn[b * T_ + tokB];
    const float4* pA = (const float4*)(x + ((size_t)b * T_ + tokA) * C_) + ahalf;
    const float4* pB = (const float4*)(x + ((size_t)b * T_ + tokB) * C_) + ahalf;

    float acc[8][8];
    #pragma unroll
    for (int i = 0; i < 8; i++)
        #pragma unroll
        for (int j = 0; j < 8; j++) acc[i][j] = 0.f;

    int ty = tid >> 4, tx = tid & 15;

    for (int k0 = 0; k0 < C_; k0 += 8) {
        float4 va = pA[k0 >> 2];
        float4 vb = pB[k0 >> 2];
        __syncthreads();
        As[ahalf * 4 + 0][arow] = va.x * invA;
        As[ahalf * 4 + 1][arow] = va.y * invA;
        As[ahalf * 4 + 2][arow] = va.z * invA;
        As[ahalf * 4 + 3][arow] = va.w * invA;
        Bs[ahalf * 4 + 0][arow] = vb.x * invB;
        Bs[ahalf * 4 + 1][arow] = vb.y * invB;
        Bs[ahalf * 4 + 2][arow] = vb.z * invB;
        Bs[ahalf * 4 + 3][arow] = vb.w * invB;
        __syncthreads();
        #pragma unroll
        for (int kk = 0; kk < 8; kk++) {
            float a[8], bb[8];
            *(float4*)&a[0]  = *(const float4*)&As[kk][ty * 4];
            *(float4*)&a[4]  = *(const float4*)&As[kk][ty * 4 + 64];
            *(float4*)&bb[0] = *(const float4*)&Bs[kk][tx * 4];
            *(float4*)&bb[4] = *(const float4*)&Bs[kk][tx * 4 + 64];
            #pragma unroll
            for (int i = 0; i < 8; i++)
                #pragma unroll
                for (int j = 0; j < 8; j++)
                    acc[i][j] = fmaf(a[i], bb[j], acc[i][j]);
        }
    }

    // epilogue: row-wise (max, first-argmax) over this 128-col tile,
    // reduce across the 16 lanes sharing each row, atomicMax to global.
    #pragma unroll
    for (int i = 0; i < 8; i++) {
        int r = ty * 4 + (i < 4 ? i : 60 + i);   // 64 + (i-4)
        unsigned long long best = 0ull;
        #pragma unroll
        for (int j = 0; j < 8; j++) {
            int cn = n0 + tx * 4 + (j < 4 ? j : 60 + j);
            unsigned long long key =
                ((unsigned long long)ordf(acc[i][j]) << 32) |
                (unsigned long long)(0xFFFFFFFFu - (unsigned int)cn); // ties -> lower k wins
            if (key > best) best = key;
        }
        #pragma unroll
        for (int o = 8; o; o >>= 1) {
            unsigned long long other = __shfl_xor_sync(0xffffffffu, best, o);
            if (other > best) best = other;
        }
        if (tx == 0) {
            int tok = g_nonkept[b * NK_ + m0 + r];
            atomicMax(&g_arg[(size_t)b * T_ + tok], best);
        }
    }
}

// ---------------------------------------------------------------
// 5) decode argmax + self-assign override for kept tokens
// ---------------------------------------------------------------
__global__ void decode_kernel() {
    int i = blockIdx.x * 256 + threadIdx.x;
    if (i >= BT) return;
    int kr = g_keeprank[i];
    g_assign[i] = (kr >= 0)
        ? kr
        : (int)(0xFFFFFFFFu - (unsigned int)(g_arg[i] & 0xFFFFFFFFull));
}

// ---------------------------------------------------------------
// 6) scatter-add segment sums (one block per token)
// ---------------------------------------------------------------
__global__ void scatter_kernel(const float* __restrict__ x) {
    int tok = blockIdx.x;
    int b = tok >> 12;                 // / T_
    int a = g_assign[tok];
    float* dst = g_sums + ((size_t)(b * K_ + a)) * C_;
    const float* src = x + (size_t)tok * C_;
    for (int i = threadIdx.x; i < C_; i += 256) atomicAdd(dst + i, src[i]);
    if (threadIdx.x == 0) atomicAdd(&g_cnt[b * K_ + a], 1.0f);
}

// ---------------------------------------------------------------
// 7) blend: out = 0.85 * x_kept + 0.15 * (sums / cnt)
// ---------------------------------------------------------------
__global__ void out_kernel(const float* __restrict__ x, float* __restrict__ out) {
    int i = blockIdx.x;                // b*K + k
    int b = i >> 11;                   // / K_
    int tok = g_keep[i];
    float invc = 1.0f / g_cnt[i];
    const float4* xk = (const float4*)(x + ((size_t)b * T_ + tok) * C_);
    const float4* s  = (const float4*)(g_sums + (size_t)i * C_);
    float4* o = (float4*)out + (size_t)i * (C_ / 4);
    for (int j = threadIdx.x; j < C_ / 4; j += 256) {
        float4 xv = xk[j], sv = s[j], r;
        r.x = 0.85f * xv.x + 0.15f * (sv.x * invc);
        r.y = 0.85f * xv.y + 0.15f * (sv.y * invc);
        r.z = 0.85f * xv.z + 0.15f * (sv.z * invc);
        r.w = 0.85f * xv.w + 0.15f * (sv.w * invc);
        o[j] = r;
    }
}

// ---------------------------------------------------------------
extern "C" void kernel_launch(void* const* d_in, const int* in_sizes, int n_in,
                              void* d_out, int out_size) {
    const float* x = (const float*)d_in[0];
    float* out = (float*)d_out;

    score_kernel<<<BT, 256>>>(x);
    topk_kernel<<<B_, 1024>>>();
    zero_kernel<<<4096, 1024>>>();
    {
        dim3 grid(16, 16, B_);
        simarg_kernel<<<grid, 256>>>(x);
    }
    decode_kernel<<<(BT + 255) / 256, 256>>>();
    scatter_kernel<<<BT, 256>>>(x);
    out_kernel<<<BK, 256>>>(x, out);
}

// round 5
// speedup vs baseline: 1.1143x; 1.1143x over previous
#include <cuda_runtime.h>
#include <cuda_bf16.h>
#include <cstdint>
#include <math.h>

#define B_   8
#define T_   4096
#define C_   1024
#define K_   2048
#define NK_  2048
#define BT   (B_ * T_)
#define BK   (B_ * K_)

#define FLAG_CAP 2048
#define EPS_GAP  2e-4f

// ---- scratch (__device__ globals: allocation-free) ----
__device__ float  g_score[BT];
__device__ float  g_invn[BT];
__device__ int    g_keep[BK];
__device__ int    g_nonkept[B_ * NK_];
__device__ int    g_keeprank[BT];
__device__ unsigned long long g_arg[BT];
__device__ int    g_assign[BT];
__device__ int    g_icnt[BK];
__device__ int    g_off[BK];
__device__ int    g_cursor[BK];
__device__ int    g_members[BT];
__device__ int    g_flagcntb[B_];
__device__ int    g_flagtokb[B_][FLAG_CAP];
// normalized bf16 hi/lo split matrices (gathered): A = nonkept rows, B = kept rows
__device__ __nv_bfloat16 g_Ahi[(size_t)B_ * 2048 * 1024];
__device__ __nv_bfloat16 g_Alo[(size_t)B_ * 2048 * 1024];
__device__ __nv_bfloat16 g_Bhi[(size_t)B_ * 2048 * 1024];
__device__ __nv_bfloat16 g_Blo[(size_t)B_ * 2048 * 1024];

__device__ __forceinline__ unsigned int ordf(float f) {
    unsigned int u = __float_as_uint(f);
    return (u & 0x80000000u) ? ~u : (u | 0x80000000u);
}
__device__ __forceinline__ float iordf(unsigned int u) {
    return __uint_as_float((u & 0x80000000u) ? (u & 0x7FFFFFFFu) : ~u);
}

// =====================  async-copy / mma helpers  =====================
__device__ __forceinline__ uint32_t smem_u32(const void* p) {
    uint32_t a;
    asm("{ .reg .u64 t; cvta.to.shared.u64 t, %1; cvt.u32.u64 %0, t; }" : "=r"(a) : "l"(p));
    return a;
}
__device__ __forceinline__ void cp16(uint32_t dst, const void* src) {
    asm volatile("cp.async.cg.shared.global [%0], [%1], 16;" :: "r"(dst), "l"(src) : "memory");
}
__device__ __forceinline__ void cp_commit() { asm volatile("cp.async.commit_group;" ::: "memory"); }
__device__ __forceinline__ void cp_wait1()  { asm volatile("cp.async.wait_group 1;" ::: "memory"); }
__device__ __forceinline__ void cp_wait0()  { asm volatile("cp.async.wait_group 0;" ::: "memory"); }

#define LDSM_X4(r0, r1, r2, r3, addr) \
    asm volatile("ldmatrix.sync.aligned.m8n8.x4.shared.b16 {%0,%1,%2,%3}, [%4];" \
        : "=r"(r0), "=r"(r1), "=r"(r2), "=r"(r3) : "r"(addr))
#define MMA16816(c, a, b0, b1) \
    asm volatile("mma.sync.aligned.m16n8k16.row.col.f32.bf16.bf16.f32 " \
        "{%0,%1,%2,%3}, {%4,%5,%6,%7}, {%8,%9}, {%0,%1,%2,%3};" \
        : "+f"((c)[0]), "+f"((c)[1]), "+f"((c)[2]), "+f"((c)[3]) \
        : "r"((a)[0]), "r"((a)[1]), "r"((a)[2]), "r"((a)[3]), "r"(b0), "r"(b1))

// ---------------------------------------------------------------
// 1) per-token squared-L2 score (fp64 accumulate) + inverse norm
// ---------------------------------------------------------------
__global__ void score_kernel(const float* __restrict__ x) {
    int tok = blockIdx.x;
    const float* xp = x + (size_t)tok * C_;
    double s = 0.0;
    for (int i = threadIdx.x; i < C_; i += 256) {
        double v = (double)xp[i];
        s += v * v;
    }
    #pragma unroll
    for (int o = 16; o; o >>= 1) s += __shfl_down_sync(0xffffffffu, s, o);
    __shared__ double sm[8];
    if ((threadIdx.x & 31) == 0) sm[threadIdx.x >> 5] = s;
    __syncthreads();
    if (threadIdx.x < 8) {
        double v = sm[threadIdx.x];
        #pragma unroll
        for (int o = 4; o; o >>= 1) v += __shfl_down_sync(0xffu, v, o);
        if (threadIdx.x == 0) {
            float fs = (float)v;
            if ((tok & (T_ - 1)) == 0) fs = 3.402823466e+38f;   // CLS protection
            g_score[tok] = fs;
            g_invn[tok]  = 1.0f / ((float)sqrt(v) + 1e-12f);
        }
    }
}

// ---------------------------------------------------------------
// 2) per-batch exact top-K via bitonic sort
// ---------------------------------------------------------------
__global__ void __launch_bounds__(1024) topk_kernel() {
    int b   = blockIdx.x;
    int tid = threadIdx.x;
    __shared__ unsigned long long skey[T_];

    for (int i = tid; i < T_; i += 1024) {
        unsigned long long k =
            ((unsigned long long)(~ordf(g_score[b * T_ + i])) << 32) | (unsigned int)i;
        skey[i] = k;
        g_keeprank[b * T_ + i] = -1;
    }
    __syncthreads();

    for (int k = 2; k <= T_; k <<= 1) {
        for (int j = k >> 1; j > 0; j >>= 1) {
            for (int i = tid; i < T_; i += 1024) {
                int l = i ^ j;
                if (l > i) {
                    unsigned long long a = skey[i], c = skey[l];
                    bool asc = ((i & k) == 0);
                    if ((a > c) == asc) { skey[i] = c; skey[l] = a; }
                }
            }
            __syncthreads();
        }
    }

    int myi[4];
    #pragma unroll
    for (int r = 0; r < 4; r++)
        myi[r] = (int)(unsigned int)(skey[tid + r * 1024] & 0xFFFFFFFFull);
    __syncthreads();
    int* si = (int*)skey;
    #pragma unroll
    for (int r = 0; r < 4; r++) si[tid + r * 1024] = myi[r];
    __syncthreads();

    for (int k = 2; k <= 2048; k <<= 1) {
        for (int j = k >> 1; j > 0; j >>= 1) {
            for (int base = 0; base < T_; base += 2048) {
                for (int i = tid; i < 2048; i += 1024) {
                    int l = i ^ j;
                    if (l > i) {
                        int a = si[base + i], c = si[base + l];
                        bool asc = ((i & k) == 0);
                        if ((a > c) == asc) { si[base + i] = c; si[base + l] = a; }
                    }
                }
            }
            __syncthreads();
        }
    }

    for (int i = tid; i < K_; i += 1024) {
        int t = si[i];
        g_keep[b * K_ + i] = t;
        g_keeprank[b * T_ + t] = i;
    }
    for (int i = tid; i < NK_; i += 1024)
        g_nonkept[b * NK_ + i] = si[2048 + i];
}

// ---------------------------------------------------------------
// 3) gather + normalize + bf16 hi/lo split
// ---------------------------------------------------------------
__global__ void prep_kernel(const float* __restrict__ x) {
    int rid = blockIdx.x;               // [0, 32768)
    int list = rid >> 14;               // 0 = nonkept(A), 1 = kept(B)
    int b = (rid >> 11) & 7;
    int r = rid & 2047;
    int tok = list ? g_keep[b * K_ + r] : g_nonkept[b * NK_ + r];
    float inv = g_invn[b * T_ + tok];
    const float4* src = (const float4*)(x + ((size_t)(b * T_ + tok)) * C_);
    size_t rb = ((size_t)(b * 2048 + r)) * 1024;
    __nv_bfloat162* dh = (__nv_bfloat162*)((list ? g_Bhi : g_Ahi) + rb);
    __nv_bfloat162* dl = (__nv_bfloat162*)((list ? g_Blo : g_Alo) + rb);
    for (int j = threadIdx.x; j < 256; j += 128) {
        float4 v = src[j];
        v.x *= inv; v.y *= inv; v.z *= inv; v.w *= inv;
        __nv_bfloat16 h0 = __float2bfloat16(v.x);
        __nv_bfloat16 h1 = __float2bfloat16(v.y);
        __nv_bfloat16 h2 = __float2bfloat16(v.z);
        __nv_bfloat16 h3 = __float2bfloat16(v.w);
        __nv_bfloat16 l0 = __float2bfloat16(v.x - __bfloat162float(h0));
        __nv_bfloat16 l1 = __float2bfloat16(v.y - __bfloat162float(h1));
        __nv_bfloat16 l2 = __float2bfloat16(v.z - __bfloat162float(h2));
        __nv_bfloat16 l3 = __float2bfloat16(v.w - __bfloat162float(h3));
        dh[j * 2]     = __halves2bfloat162(h0, h1);
        dh[j * 2 + 1] = __halves2bfloat162(h2, h3);
        dl[j * 2]     = __halves2bfloat162(l0, l1);
        dl[j * 2 + 1] = __halves2bfloat162(l2, l3);
    }
}

// ---------------------------------------------------------------
// 4) zero counters
// ---------------------------------------------------------------
__global__ void zero_kernel() {
    int i = blockIdx.x * 256 + threadIdx.x;
    if (i < BK) g_icnt[i] = 0;
    if (i < B_) g_flagcntb[i] = 0;
}

// ---------------------------------------------------------------
// 5) mma.sync bf16x3 sim GEMM + per-row top-2 epilogue
//    CTA: 128 m-rows; loops 16 n-steps of 128; k in chunks of 64.
// ---------------------------------------------------------------
#define STRIDE   144
#define TILE_B   (128 * STRIDE)        // 18432
#define STAGE_B  (4 * TILE_B)          // 73728
#define SMEM_TOT (2 * STAGE_B)         // 147456

__device__ __forceinline__ void load_stage(int ns, int kc, int sidx,
                                           uint32_t sbase, int b, int m0, int tid) {
    uint32_t st = sbase + (uint32_t)sidx * STAGE_B;
    int n0 = ns * 128, k0 = kc * 64;
    size_t arow0 = ((size_t)(b * 2048 + m0)) * 1024 + k0;
    size_t brow0 = ((size_t)(b * 2048 + n0)) * 1024 + k0;
    const __nv_bfloat16* srcs[4] = { g_Ahi + arow0, g_Alo + arow0,
                                     g_Bhi + brow0, g_Blo + brow0 };
    #pragma unroll
    for (int mat = 0; mat < 4; mat++) {
        const __nv_bfloat16* base = srcs[mat];
        uint32_t dmat = st + (uint32_t)mat * TILE_B;
        #pragma unroll
        for (int u = 0; u < 4; u++) {
            int i = u * 256 + tid;
            int row = i >> 3, j = i & 7;
            cp16(dmat + (uint32_t)(row * STRIDE + j * 16),
                 base + (size_t)row * 1024 + j * 8);
        }
    }
    cp_commit();
}

__global__ void __launch_bounds__(256, 1) simarg_mma() {
    extern __shared__ char smem[];
    uint32_t sbase = smem_u32(smem);
    int tid = threadIdx.x;
    int wid = tid >> 5, lane = tid & 31;
    int wm = wid >> 2, wn = wid & 3;     // warp tile: 64m x 32n
    int b  = blockIdx.y;
    int m0 = blockIdx.x * 128;

    // lane-derived ldmatrix row/k offsets (non-trans for both A and B)
    int arow = (lane & 7) + ((lane >> 3) & 1) * 8;   // lanes 0-15: rows 0-15 @k0; 16-31: rows @k+8
    int ak8  = (lane >> 4);
    int brow = (lane & 7) + (lane >> 4) * 8;         // lanes 0-7: n0-7@k0; 8-15: n0-7@k8; 16-23: n8-15@k0; 24-31: n8-15@k8
    int bk8  = (lane >> 3) & 1;

    unsigned long long tb[8], ts[8];
    #pragma unroll
    for (int s = 0; s < 8; s++) { tb[s] = 0ull; ts[s] = 0ull; }

    load_stage(0, 0, 0, sbase, b, m0, tid);

    float acc[4][4][4];
    int g = 0;
    for (int ns = 0; ns < 16; ns++) {
        #pragma unroll
        for (int mi = 0; mi < 4; mi++)
            #pragma unroll
            for (int ni = 0; ni < 4; ni++)
                #pragma unroll
                for (int r = 0; r < 4; r++) acc[mi][ni][r] = 0.f;

        for (int kc = 0; kc < 16; kc++) {
            int s = g & 1;
            if (g < 255) {
                int gn = g + 1;
                load_stage(gn >> 4, gn & 15, s ^ 1, sbase, b, m0, tid);
                cp_wait1();
            } else cp_wait0();
            __syncthreads();

            uint32_t st = sbase + (uint32_t)s * STAGE_B;
            #pragma unroll
            for (int q = 0; q < 4; q++) {      // 4 k16 steps within 64-chunk
                int k0 = q * 16;
                uint32_t ahi[4][4], alo[4][4], bhi[2][4], blo[2][4];
                #pragma unroll
                for (int mi = 0; mi < 4; mi++) {
                    uint32_t ra = (uint32_t)((wm * 64 + mi * 16 + arow) * STRIDE
                                             + (k0 + ak8 * 8) * 2);
                    LDSM_X4(ahi[mi][0], ahi[mi][1], ahi[mi][2], ahi[mi][3], st + ra);
                    LDSM_X4(alo[mi][0], alo[mi][1], alo[mi][2], alo[mi][3], st + TILE_B + ra);
                }
                #pragma unroll
                for (int nj = 0; nj < 2; nj++) {
                    uint32_t rb = (uint32_t)((wn * 32 + nj * 16 + brow) * STRIDE
                                             + (k0 + bk8 * 8) * 2);
                    LDSM_X4(bhi[nj][0], bhi[nj][1], bhi[nj][2], bhi[nj][3], st + 2 * TILE_B + rb);
                    LDSM_X4(blo[nj][0], blo[nj][1], blo[nj][2], blo[nj][3], st + 3 * TILE_B + rb);
                }
                #pragma unroll
                for (int mi = 0; mi < 4; mi++)
                    #pragma unroll
                    for (int ni = 0; ni < 4; ni++) {
                        int nj = ni >> 1, o = (ni & 1) * 2;
                        MMA16816(acc[mi][ni], ahi[mi], bhi[nj][o], bhi[nj][o + 1]);
                        MMA16816(acc[mi][ni], ahi[mi], blo[nj][o], blo[nj][o + 1]);
                        MMA16816(acc[mi][ni], alo[mi], bhi[nj][o], bhi[nj][o + 1]);
                    }
            }
            __syncthreads();
            g++;
        }

        // fold this n-step into per-thread top-2
        #pragma unroll
        for (int mi = 0; mi < 4; mi++)
            #pragma unroll
            for (int h = 0; h < 2; h++) {
                int slot = mi * 2 + h;
                #pragma unroll
                for (int ni = 0; ni < 4; ni++)
                    #pragma unroll
                    for (int cp = 0; cp < 2; cp++) {
                        float v = acc[mi][ni][h * 2 + cp];
                        int col = ns * 128 + wn * 32 + ni * 8 + (lane & 3) * 2 + cp;
                        unsigned long long key =
                            ((unsigned long long)ordf(v) << 32) |
                            (unsigned long long)(0xFFFFFFFFu - (unsigned int)col);
                        if (key > tb[slot]) { ts[slot] = tb[slot]; tb[slot] = key; }
                        else if (key > ts[slot]) ts[slot] = key;
                    }
            }
    }

    // cross-thread top-2 merge via smem (reuse stage buffers)
    unsigned long long* pp = (unsigned long long*)smem;
    #pragma unroll
    for (int slot = 0; slot < 8; slot++) {
        int mi = slot >> 1, h = slot & 1;
        int row = wm * 64 + mi * 16 + h * 8 + (lane >> 2);
        int idx = wn * 4 + (lane & 3);
        pp[(row * 16 + idx) * 2]     = tb[slot];
        pp[(row * 16 + idx) * 2 + 1] = ts[slot];
    }
    __syncthreads();
    if (tid < 128) {
        unsigned long long Bk = 0ull, Sk = 0ull;
        for (int i = 0; i < 16; i++) {
            unsigned long long b2 = pp[(tid * 16 + i) * 2];
            unsigned long long s2 = pp[(tid * 16 + i) * 2 + 1];
            unsigned long long nb = Bk > b2 ? Bk : b2;
            unsigned long long mn = Bk > b2 ? b2 : Bk;
            unsigned long long s3 = Sk > s2 ? Sk : s2;
            Sk = s3 > mn ? s3 : mn;
            Bk = nb;
        }
        int tok = g_nonkept[b * NK_ + m0 + tid];
        float fb = iordf((unsigned int)(Bk >> 32));
        float fs = iordf((unsigned int)(Sk >> 32));
        if (fb - fs < EPS_GAP) {
            int idx = atomicAdd(&g_flagcntb[b], 1);
            if (idx < FLAG_CAP) {
                g_flagtokb[b][idx] = b * T_ + tok;
                g_arg[(size_t)b * T_ + tok] = 0ull;      // repair will fill
            } else g_arg[(size_t)b * T_ + tok] = Bk;
        } else g_arg[(size_t)b * T_ + tok] = Bk;
    }
}

// ---------------------------------------------------------------
// 6) exact fp32 re-argmax for near-tie rows (centers L2-resident)
// ---------------------------------------------------------------
__global__ void __launch_bounds__(256) repair_kernel(const float* __restrict__ x) {
    __shared__ float4 feat[8][256];     // 8 tokens x 1024 dims
    int b = blockIdx.y, chunk = blockIdx.x;   // 16 chunks of 128 centers
    int tid = threadIdx.x, warp = tid >> 5, lane = tid & 31;
    int cnt = g_flagcntb[b];
    if (cnt > FLAG_CAP) cnt = FLAG_CAP;

    for (int p0 = 0; p0 < cnt; p0 += 8) {
        int np = cnt - p0; if (np > 8) np = 8;
        for (int i = tid; i < np * 256; i += 256) {
            int tt = i >> 8, j = i & 255;
            int gi = g_flagtokb[b][p0 + tt];
            float inv = g_invn[gi];
            float4 v = ((const float4*)x)[(size_t)gi * 256 + j];
            v.x *= inv; v.y *= inv; v.z *= inv; v.w *= inv;
            feat[tt][j] = v;
        }
        __syncthreads();
        if (warp < np) {
            unsigned long long best = 0ull;
            for (int c = chunk * 128; c < chunk * 128 + 128; c++) {
                int ct = g_keep[b * K_ + c];
                const float4* cp = (const float4*)(x + ((size_t)(b * T_ + ct)) * C_);
                float s = 0.f;
                for (int j = lane; j < 256; j += 32) {
                    float4 v = cp[j], f = feat[warp][j];
                    s += f.x * v.x + f.y * v.y + f.z * v.z + f.w * v.w;
                }
                #pragma unroll
                for (int o = 16; o; o >>= 1) s += __shfl_down_sync(0xffffffffu, s, o);
                if (lane == 0) {
                    s *= g_invn[b * T_ + ct];
                    unsigned long long key =
                        ((unsigned long long)ordf(s) << 32) |
                        (unsigned long long)(0xFFFFFFFFu - (unsigned int)c);
                    if (key > best) best = key;
                }
            }
            if (lane == 0)
                atomicMax(&g_arg[(size_t)g_flagtokb[b][p0 + warp]], best);
        }
        __syncthreads();
    }
}

// ---------------------------------------------------------------
// 7) decode argmax + self-assign override + cluster-size histogram
// ---------------------------------------------------------------
__global__ void decode_kernel() {
    int i = blockIdx.x * 256 + threadIdx.x;
    if (i >= BT) return;
    int kr = g_keeprank[i];
    int a = (kr >= 0)
        ? kr
        : (int)(0xFFFFFFFFu - (unsigned int)(g_arg[i] & 0xFFFFFFFFull));
    g_assign[i] = a;
    atomicAdd(&g_icnt[(i >> 12) * K_ + a], 1);
}

// ---------------------------------------------------------------
// 8) per-batch exclusive scan of cluster sizes -> offsets
// ---------------------------------------------------------------
__global__ void __launch_bounds__(1024) scan_kernel() {
    int b = blockIdx.x, tid = threadIdx.x;
    __shared__ int s0[2048], s1[2048];
    s0[tid] = g_icnt[b * K_ + tid];
    s0[tid + 1024] = g_icnt[b * K_ + tid + 1024];
    __syncthreads();
    int* src = s0; int* dst = s1;
    for (int d = 1; d < 2048; d <<= 1) {
        for (int i = tid; i < 2048; i += 1024) {
            int v = src[i];
            if (i >= d) v += src[i - d];
            dst[i] = v;
        }
        __syncthreads();
        int* t = src; src = dst; dst = t;
    }
    for (int i = tid; i < 2048; i += 1024) {
        int off = src[i] - g_icnt[b * K_ + i];
        g_off[b * K_ + i] = off;
        g_cursor[b * K_ + i] = off;
    }
}

// ---------------------------------------------------------------
// 9) fill member lists
// ---------------------------------------------------------------
__global__ void fill_kernel() {
    int i = blockIdx.x * 256 + threadIdx.x;
    if (i >= BT) return;
    int b = i >> 12;
    int a = g_assign[i];
    int slot = atomicAdd(&g_cursor[b * K_ + a], 1);
    g_members[b * T_ + slot] = i & (T_ - 1);
}

// ---------------------------------------------------------------
// 10) per-center member sum + blend
// ---------------------------------------------------------------
__global__ void out_kernel(const float* __restrict__ x, float* __restrict__ out) {
    int i = blockIdx.x;                // b*K + k
    int b = i >> 11;
    int tidx = threadIdx.x;
    int cnt = g_icnt[i];
    int off = g_off[i];
    float4 acc = make_float4(0.f, 0.f, 0.f, 0.f);
    for (int m = 0; m < cnt; m++) {
        int tok = g_members[b * T_ + off + m];
        float4 v = ((const float4*)(x + ((size_t)(b * T_ + tok)) * C_))[tidx];
        acc.x += v.x; acc.y += v.y; acc.z += v.z; acc.w += v.w;
    }
    int ktok = g_keep[i];
    float4 xk = ((const float4*)(x + ((size_t)(b * T_ + ktok)) * C_))[tidx];
    float invc = 1.0f / (float)cnt;
    float4 r;
    r.x = 0.85f * xk.x + 0.15f * acc.x * invc;
    r.y = 0.85f * xk.y + 0.15f * acc.y * invc;
    r.z = 0.85f * xk.z + 0.15f * acc.z * invc;
    r.w = 0.85f * xk.w + 0.15f * acc.w * invc;
    ((float4*)out)[(size_t)i * 256 + tidx] = r;
}

// ---------------------------------------------------------------
extern "C" void kernel_launch(void* const* d_in, const int* in_sizes, int n_in,
                              void* d_out, int out_size) {
    const float* x = (const float*)d_in[0];
    float* out = (float*)d_out;

    cudaFuncSetAttribute(simarg_mma, cudaFuncAttributeMaxDynamicSharedMemorySize, SMEM_TOT);

    score_kernel<<<BT, 256>>>(x);
    topk_kernel<<<B_, 1024>>>();
    prep_kernel<<<32768, 128>>>(x);
    zero_kernel<<<(BK + 255) / 256, 256>>>();
    {
        dim3 grid(16, B_);
        simarg_mma<<<grid, 256, SMEM_TOT>>>();
    }
    {
        dim3 grid(16, B_);
        repair_kernel<<<grid, 256>>>(x);
    }
    decode_kernel<<<(BT + 255) / 256, 256>>>();
    scan_kernel<<<B_, 1024>>>();
    fill_kernel<<<(BT + 255) / 256, 256>>>();
    out_kernel<<<BK, 256>>>(x, out);
}

// round 6
// speedup vs baseline: 2.2334x; 2.0043x over previous
#include <cuda_runtime.h>
#include <cuda_bf16.h>
#include <cstdint>
#include <math.h>

#define B_   8
#define T_   4096
#define C_   1024
#define K_   2048
#define NK_  2048
#define BT   (B_ * T_)
#define BK   (B_ * K_)

#define FLAG_CAP 2048
#define WIN      1e-3f      // candidate window: 2x max 1-stream bf16 sim error, with margin
#define NCAND    8

// ---- scratch (__device__ globals: allocation-free) ----
__device__ float  g_score[BT];
__device__ float  g_invn[BT];
__device__ int    g_keep[BK];
__device__ int    g_nonkept[B_ * NK_];
__device__ int    g_keeprank[BT];
__device__ unsigned long long g_arg[BT];
__device__ int    g_assign[BT];
__device__ int    g_icnt[BK];
__device__ int    g_off[BK];
__device__ int    g_cursor[BK];
__device__ int    g_members[BT];
__device__ int    g_flagcntb[B_];
__device__ int    g_flagtokb[B_][FLAG_CAP];
__device__ unsigned char g_flagn[B_][FLAG_CAP];
__device__ short  g_flagcand[B_][FLAG_CAP][NCAND];
// normalized bf16 matrices (gathered): A = nonkept rows, B = kept rows
__device__ __nv_bfloat16 g_Ahi[(size_t)B_ * 2048 * 1024];
__device__ __nv_bfloat16 g_Bhi[(size_t)B_ * 2048 * 1024];

__device__ __forceinline__ unsigned int ordf(float f) {
    unsigned int u = __float_as_uint(f);
    return (u & 0x80000000u) ? ~u : (u | 0x80000000u);
}
__device__ __forceinline__ float iordf(unsigned int u) {
    return __uint_as_float((u & 0x80000000u) ? (u & 0x7FFFFFFFu) : ~u);
}

// =====================  async-copy / mma helpers  =====================
__device__ __forceinline__ uint32_t smem_u32(const void* p) {
    uint32_t a;
    asm("{ .reg .u64 t; cvta.to.shared.u64 t, %1; cvt.u32.u64 %0, t; }" : "=r"(a) : "l"(p));
    return a;
}
__device__ __forceinline__ void cp16(uint32_t dst, const void* src) {
    asm volatile("cp.async.cg.shared.global [%0], [%1], 16;" :: "r"(dst), "l"(src) : "memory");
}
__device__ __forceinline__ void cp_commit() { asm volatile("cp.async.commit_group;" ::: "memory"); }
__device__ __forceinline__ void cp_wait1()  { asm volatile("cp.async.wait_group 1;" ::: "memory"); }
__device__ __forceinline__ void cp_wait0()  { asm volatile("cp.async.wait_group 0;" ::: "memory"); }

#define LDSM_X4(r0, r1, r2, r3, addr) \
    asm volatile("ldmatrix.sync.aligned.m8n8.x4.shared.b16 {%0,%1,%2,%3}, [%4];" \
        : "=r"(r0), "=r"(r1), "=r"(r2), "=r"(r3) : "r"(addr))
#define MMA16816(c, a, b0, b1) \
    asm volatile("mma.sync.aligned.m16n8k16.row.col.f32.bf16.bf16.f32 " \
        "{%0,%1,%2,%3}, {%4,%5,%6,%7}, {%8,%9}, {%0,%1,%2,%3};" \
        : "+f"((c)[0]), "+f"((c)[1]), "+f"((c)[2]), "+f"((c)[3]) \
        : "r"((a)[0]), "r"((a)[1]), "r"((a)[2]), "r"((a)[3]), "r"(b0), "r"(b1))

// ---------------------------------------------------------------
// 1) per-token squared-L2 score (fp64 accumulate) + inverse norm
// ---------------------------------------------------------------
__global__ void score_kernel(const float* __restrict__ x) {
    int tok = blockIdx.x;
    const float* xp = x + (size_t)tok * C_;
    double s = 0.0;
    for (int i = threadIdx.x; i < C_; i += 256) {
        double v = (double)xp[i];
        s += v * v;
    }
    #pragma unroll
    for (int o = 16; o; o >>= 1) s += __shfl_down_sync(0xffffffffu, s, o);
    __shared__ double sm[8];
    if ((threadIdx.x & 31) == 0) sm[threadIdx.x >> 5] = s;
    __syncthreads();
    if (threadIdx.x < 8) {
        double v = sm[threadIdx.x];
        #pragma unroll
        for (int o = 4; o; o >>= 1) v += __shfl_down_sync(0xffu, v, o);
        if (threadIdx.x == 0) {
            float fs = (float)v;
            if ((tok & (T_ - 1)) == 0) fs = 3.402823466e+38f;   // CLS protection
            g_score[tok] = fs;
            g_invn[tok]  = 1.0f / ((float)sqrt(v) + 1e-12f);
        }
    }
}

// ---------------------------------------------------------------
// 2) per-batch exact top-K via bitonic sort
// ---------------------------------------------------------------
__global__ void __launch_bounds__(1024) topk_kernel() {
    int b   = blockIdx.x;
    int tid = threadIdx.x;
    __shared__ unsigned long long skey[T_];

    for (int i = tid; i < T_; i += 1024) {
        unsigned long long k =
            ((unsigned long long)(~ordf(g_score[b * T_ + i])) << 32) | (unsigned int)i;
        skey[i] = k;
        g_keeprank[b * T_ + i] = -1;
    }
    __syncthreads();

    for (int k = 2; k <= T_; k <<= 1) {
        for (int j = k >> 1; j > 0; j >>= 1) {
            for (int i = tid; i < T_; i += 1024) {
                int l = i ^ j;
                if (l > i) {
                    unsigned long long a = skey[i], c = skey[l];
                    bool asc = ((i & k) == 0);
                    if ((a > c) == asc) { skey[i] = c; skey[l] = a; }
                }
            }
            __syncthreads();
        }
    }

    int myi[4];
    #pragma unroll
    for (int r = 0; r < 4; r++)
        myi[r] = (int)(unsigned int)(skey[tid + r * 1024] & 0xFFFFFFFFull);
    __syncthreads();
    int* si = (int*)skey;
    #pragma unroll
    for (int r = 0; r < 4; r++) si[tid + r * 1024] = myi[r];
    __syncthreads();

    for (int k = 2; k <= 2048; k <<= 1) {
        for (int j = k >> 1; j > 0; j >>= 1) {
            for (int base = 0; base < T_; base += 2048) {
                for (int i = tid; i < 2048; i += 1024) {
                    int l = i ^ j;
                    if (l > i) {
                        int a = si[base + i], c = si[base + l];
                        bool asc = ((i & k) == 0);
                        if ((a > c) == asc) { si[base + i] = c; si[base + l] = a; }
                    }
                }
            }
            __syncthreads();
        }
    }

    for (int i = tid; i < K_; i += 1024) {
        int t = si[i];
        g_keep[b * K_ + i] = t;
        g_keeprank[b * T_ + t] = i;
    }
    for (int i = tid; i < NK_; i += 1024)
        g_nonkept[b * NK_ + i] = si[2048 + i];
}

// ---------------------------------------------------------------
// 3) gather + normalize + bf16 round (hi only)
// ---------------------------------------------------------------
__global__ void prep_kernel(const float* __restrict__ x) {
    int rid = blockIdx.x;               // [0, 32768)
    int list = rid >> 14;               // 0 = nonkept(A), 1 = kept(B)
    int b = (rid >> 11) & 7;
    int r = rid & 2047;
    int tok = list ? g_keep[b * K_ + r] : g_nonkept[b * NK_ + r];
    float inv = g_invn[b * T_ + tok];
    const float4* src = (const float4*)(x + ((size_t)(b * T_ + tok)) * C_);
    size_t rb = ((size_t)(b * 2048 + r)) * 1024;
    __nv_bfloat162* dh = (__nv_bfloat162*)((list ? g_Bhi : g_Ahi) + rb);
    for (int j = threadIdx.x; j < 256; j += 128) {
        float4 v = src[j];
        v.x *= inv; v.y *= inv; v.z *= inv; v.w *= inv;
        dh[j * 2]     = __halves2bfloat162(__float2bfloat16(v.x), __float2bfloat16(v.y));
        dh[j * 2 + 1] = __halves2bfloat162(__float2bfloat16(v.z), __float2bfloat16(v.w));
    }
}

// ---------------------------------------------------------------
// 4) zero counters
// ---------------------------------------------------------------
__global__ void zero_kernel() {
    int i = blockIdx.x * 256 + threadIdx.x;
    if (i < BK) g_icnt[i] = 0;
    if (i < B_) g_flagcntb[i] = 0;
}

// ---------------------------------------------------------------
// 5) mma.sync bf16 (1-stream) sim GEMM + top-3/thread epilogue
//    CTA: 128 m-rows; loops 16 n-steps of 128; k in chunks of 64.
// ---------------------------------------------------------------
#define STRIDE   144
#define TILE_B   (128 * STRIDE)        // 18432
#define STAGE_B  (2 * TILE_B)          // 36864  (A hi + B hi)
#define SMEM_TOT (2 * STAGE_B)         // 73728

__device__ __forceinline__ void load_stage(int ns, int kc, int sidx,
                                           uint32_t sbase, int b, int m0, int tid) {
    uint32_t st = sbase + (uint32_t)sidx * STAGE_B;
    int n0 = ns * 128, k0 = kc * 64;
    size_t arow0 = ((size_t)(b * 2048 + m0)) * 1024 + k0;
    size_t brow0 = ((size_t)(b * 2048 + n0)) * 1024 + k0;
    #pragma unroll
    for (int u = 0; u < 4; u++) {
        int i = u * 256 + tid;
        int row = i >> 3, j = i & 7;
        uint32_t so = (uint32_t)(row * STRIDE + j * 16);
        cp16(st + so,          g_Ahi + arow0 + (size_t)row * 1024 + j * 8);
        cp16(st + TILE_B + so, g_Bhi + brow0 + (size_t)row * 1024 + j * 8);
    }
    cp_commit();
}

__global__ void __launch_bounds__(256, 1) simarg_mma() {
    extern __shared__ char smem[];
    uint32_t sbase = smem_u32(smem);
    int tid = threadIdx.x;
    int wid = tid >> 5, lane = tid & 31;
    int wm = wid >> 2, wn = wid & 3;     // warp tile: 64m x 32n
    int b  = blockIdx.y;
    int m0 = blockIdx.x * 128;

    int arow = (lane & 7) + ((lane >> 3) & 1) * 8;
    int ak8  = (lane >> 4);
    int brow = (lane & 7) + (lane >> 4) * 8;
    int bk8  = (lane >> 3) & 1;

    // per-thread top-3 per row-slot (8 slots)
    unsigned long long t0[8], t1[8], t2[8];
    #pragma unroll
    for (int s = 0; s < 8; s++) { t0[s] = 0ull; t1[s] = 0ull; t2[s] = 0ull; }

    load_stage(0, 0, 0, sbase, b, m0, tid);

    float acc[4][4][4];
    int g = 0;
    for (int ns = 0; ns < 16; ns++) {
        #pragma unroll
        for (int mi = 0; mi < 4; mi++)
            #pragma unroll
            for (int ni = 0; ni < 4; ni++)
                #pragma unroll
                for (int r = 0; r < 4; r++) acc[mi][ni][r] = 0.f;

        for (int kc = 0; kc < 16; kc++) {
            int s = g & 1;
            if (g < 255) {
                int gn = g + 1;
                load_stage(gn >> 4, gn & 15, s ^ 1, sbase, b, m0, tid);
                cp_wait1();
            } else cp_wait0();
            __syncthreads();

            uint32_t st = sbase + (uint32_t)s * STAGE_B;
            #pragma unroll
            for (int q = 0; q < 4; q++) {
                int k0 = q * 16;
                uint32_t ah[4][4], bh[2][4];
                #pragma unroll
                for (int mi = 0; mi < 4; mi++) {
                    uint32_t ra = (uint32_t)((wm * 64 + mi * 16 + arow) * STRIDE
                                             + (k0 + ak8 * 8) * 2);
                    LDSM_X4(ah[mi][0], ah[mi][1], ah[mi][2], ah[mi][3], st + ra);
                }
                #pragma unroll
                for (int nj = 0; nj < 2; nj++) {
                    uint32_t rb = (uint32_t)((wn * 32 + nj * 16 + brow) * STRIDE
                                             + (k0 + bk8 * 8) * 2);
                    LDSM_X4(bh[nj][0], bh[nj][1], bh[nj][2], bh[nj][3], st + TILE_B + rb);
                }
                #pragma unroll
                for (int mi = 0; mi < 4; mi++)
                    #pragma unroll
                    for (int ni = 0; ni < 4; ni++) {
                        int nj = ni >> 1, o = (ni & 1) * 2;
                        MMA16816(acc[mi][ni], ah[mi], bh[nj][o], bh[nj][o + 1]);
                    }
            }
            __syncthreads();
            g++;
        }

        // fold into per-thread top-3
        #pragma unroll
        for (int mi = 0; mi < 4; mi++)
            #pragma unroll
            for (int h = 0; h < 2; h++) {
                int slot = mi * 2 + h;
                #pragma unroll
                for (int ni = 0; ni < 4; ni++)
                    #pragma unroll
                    for (int cp = 0; cp < 2; cp++) {
                        float v = acc[mi][ni][h * 2 + cp];
                        int col = ns * 128 + wn * 32 + ni * 8 + (lane & 3) * 2 + cp;
                        unsigned long long key =
                            ((unsigned long long)ordf(v) << 32) |
                            (unsigned long long)(0xFFFFFFFFu - (unsigned int)col);
                        if (key > t0[slot]) { t2[slot] = t1[slot]; t1[slot] = t0[slot]; t0[slot] = key; }
                        else if (key > t1[slot]) { t2[slot] = t1[slot]; t1[slot] = key; }
                        else if (key > t2[slot]) t2[slot] = key;
                    }
            }
    }

    // cross-thread merge: 16 thread-groups x 3 entries per row
    unsigned long long* pp = (unsigned long long*)smem;
    #pragma unroll
    for (int slot = 0; slot < 8; slot++) {
        int mi = slot >> 1, h = slot & 1;
        int row = wm * 64 + mi * 16 + h * 8 + (lane >> 2);
        int grp = wn * 4 + (lane & 3);
        pp[row * 48 + grp * 3 + 0] = t0[slot];
        pp[row * 48 + grp * 3 + 1] = t1[slot];
        pp[row * 48 + grp * 3 + 2] = t2[slot];
    }
    __syncthreads();
    if (tid < 128) {
        unsigned long long mx = 0ull;
        for (int e = 0; e < 48; e++) {
            unsigned long long k = pp[tid * 48 + e];
            if (k > mx) mx = k;
        }
        float fmax = iordf((unsigned int)(mx >> 32));
        float thr = fmax - WIN;
        int cnt = 0;
        short cand[NCAND];
        for (int e = 0; e < 48; e++) {
            unsigned long long k = pp[tid * 48 + e];
            if (iordf((unsigned int)(k >> 32)) >= thr) {
                if (cnt < NCAND)
                    cand[cnt] = (short)(0xFFFFFFFFu - (unsigned int)(k & 0xFFFFFFFFull));
                cnt++;
            }
        }
        int tok = g_nonkept[b * NK_ + m0 + tid];
        if (cnt <= 1) {
            g_arg[(size_t)b * T_ + tok] = mx;
        } else {
            int idx = atomicAdd(&g_flagcntb[b], 1);
            g_flagtokb[b][idx] = b * T_ + tok;
            g_flagn[b][idx] = (cnt <= NCAND) ? (unsigned char)cnt : (unsigned char)255;
            for (int j = 0; j < NCAND; j++)
                g_flagcand[b][idx][j] = (j < cnt && cnt <= NCAND) ? cand[j] : 0;
            g_arg[(size_t)b * T_ + tok] = 0ull;   // repair fills
        }
    }
}

// ---------------------------------------------------------------
// 6) exact fp32 re-argmax over candidate columns (or full row)
// ---------------------------------------------------------------
__global__ void __launch_bounds__(256) repair_kernel(const float* __restrict__ x) {
    int b = blockIdx.x;
    int warp = threadIdx.x >> 5, lane = threadIdx.x & 31;
    int cnt = g_flagcntb[b];
    for (int idx = warp; idx < cnt; idx += 8) {
        int tok = g_flagtokb[b][idx];         // global token idx
        float tinv = g_invn[tok];
        float4 f[8];
        #pragma unroll
        for (int j = 0; j < 8; j++)
            f[j] = ((const float4*)x)[(size_t)tok * 256 + j * 32 + lane];
        int n = g_flagn[b][idx];
        unsigned long long best = 0ull;
        int iters = (n == 255) ? 2048 : n;
        for (int i = 0; i < iters; i++) {
            int c = (n == 255) ? i : (int)g_flagcand[b][idx][i];
            int ct = g_keep[b * K_ + c];
            const float4* cp = (const float4*)(x + ((size_t)(b * T_ + ct)) * C_);
            float s = 0.f;
            #pragma unroll
            for (int j = 0; j < 8; j++) {
                float4 v = cp[j * 32 + lane];
                s += f[j].x * v.x + f[j].y * v.y + f[j].z * v.z + f[j].w * v.w;
            }
            #pragma unroll
            for (int o = 16; o; o >>= 1) s += __shfl_down_sync(0xffffffffu, s, o);
            if (lane == 0) {
                s *= tinv * g_invn[b * T_ + ct];
                unsigned long long key =
                    ((unsigned long long)ordf(s) << 32) |
                    (unsigned long long)(0xFFFFFFFFu - (unsigned int)c);
                if (key > best) best = key;
            }
        }
        if (lane == 0) g_arg[tok] = best;
    }
}

// ---------------------------------------------------------------
// 7) decode argmax + self-assign override + cluster-size histogram
// ---------------------------------------------------------------
__global__ void decode_kernel() {
    int i = blockIdx.x * 256 + threadIdx.x;
    if (i >= BT) return;
    int kr = g_keeprank[i];
    int a = (kr >= 0)
        ? kr
        : (int)(0xFFFFFFFFu - (unsigned int)(g_arg[i] & 0xFFFFFFFFull));
    g_assign[i] = a;
    atomicAdd(&g_icnt[(i >> 12) * K_ + a], 1);
}

// ---------------------------------------------------------------
// 8) per-batch exclusive scan of cluster sizes -> offsets
// ---------------------------------------------------------------
__global__ void __launch_bounds__(1024) scan_kernel() {
    int b = blockIdx.x, tid = threadIdx.x;
    __shared__ int s0[2048], s1[2048];
    s0[tid] = g_icnt[b * K_ + tid];
    s0[tid + 1024] = g_icnt[b * K_ + tid + 1024];
    __syncthreads();
    int* src = s0; int* dst = s1;
    for (int d = 1; d < 2048; d <<= 1) {
        for (int i = tid; i < 2048; i += 1024) {
            int v = src[i];
            if (i >= d) v += src[i - d];
            dst[i] = v;
        }
        __syncthreads();
        int* t = src; src = dst; dst = t;
    }
    for (int i = tid; i < 2048; i += 1024) {
        int off = src[i] - g_icnt[b * K_ + i];
        g_off[b * K_ + i] = off;
        g_cursor[b * K_ + i] = off;
    }
}

// ---------------------------------------------------------------
// 9) fill member lists
// ---------------------------------------------------------------
__global__ void fill_kernel() {
    int i = blockIdx.x * 256 + threadIdx.x;
    if (i >= BT) return;
    int b = i >> 12;
    int a = g_assign[i];
    int slot = atomicAdd(&g_cursor[b * K_ + a], 1);
    g_members[b * T_ + slot] = i & (T_ - 1);
}

// ---------------------------------------------------------------
// 10) per-center member sum + blend
// ---------------------------------------------------------------
__global__ void out_kernel(const float* __restrict__ x, float* __restrict__ out) {
    int i = blockIdx.x;                // b*K + k
    int b = i >> 11;
    int tidx = threadIdx.x;
    int cnt = g_icnt[i];
    int off = g_off[i];
    float4 acc = make_float4(0.f, 0.f, 0.f, 0.f);
    for (int m = 0; m < cnt; m++) {
        int tok = g_members[b * T_ + off + m];
        float4 v = ((const float4*)(x + ((size_t)(b * T_ + tok)) * C_))[tidx];
        acc.x += v.x; acc.y += v.y; acc.z += v.z; acc.w += v.w;
    }
    int ktok = g_keep[i];
    float4 xk = ((const float4*)(x + ((size_t)(b * T_ + ktok)) * C_))[tidx];
    float invc = 1.0f / (float)cnt;
    float4 r;
    r.x = 0.85f * xk.x + 0.15f * acc.x * invc;
    r.y = 0.85f * xk.y + 0.15f * acc.y * invc;
    r.z = 0.85f * xk.z + 0.15f * acc.z * invc;
    r.w = 0.85f * xk.w + 0.15f * acc.w * invc;
    ((float4*)out)[(size_t)i * 256 + tidx] = r;
}

// ---------------------------------------------------------------
extern "C" void kernel_launch(void* const* d_in, const int* in_sizes, int n_in,
                              void* d_out, int out_size) {
    const float* x = (const float*)d_in[0];
    float* out = (float*)d_out;

    cudaFuncSetAttribute(simarg_mma, cudaFuncAttributeMaxDynamicSharedMemorySize, SMEM_TOT);

    score_kernel<<<BT, 256>>>(x);
    topk_kernel<<<B_, 1024>>>();
    prep_kernel<<<32768, 128>>>(x);
    zero_kernel<<<(BK + 255) / 256, 256>>>();
    {
        dim3 grid(16, B_);
        simarg_mma<<<grid, 256, SMEM_TOT>>>();
    }
    repair_kernel<<<B_, 256>>>(x);
    decode_kernel<<<(BT + 255) / 256, 256>>>();
    scan_kernel<<<B_, 1024>>>();
    fill_kernel<<<(BT + 255) / 256, 256>>>();
    out_kernel<<<BK, 256>>>(x, out);
}